// round 4
// baseline (speedup 1.0000x reference)
#include <cuda_runtime.h>
#include <cuda_bf16.h>
#include <cstdint>

#define NNODES 50000
#define DFEAT  512
#define DHID   1024
#define NCOLS  2048

// ---------------- device scratch ----------------
__device__ __align__(16) float g_uv[(size_t)NNODES * NCOLS];          // node GEMM output [N, 2048]
__device__ __align__(16) __nv_bfloat16 g_xhi[(size_t)NNODES * DFEAT];
__device__ __align__(16) __nv_bfloat16 g_xlo[(size_t)NNODES * DFEAT];
__device__ __align__(16) __nv_bfloat16 g_bhi[(size_t)NCOLS * DFEAT];  // W1^T hi [2048][512]
__device__ __align__(16) __nv_bfloat16 g_blo[(size_t)NCOLS * DFEAT];

__device__ __forceinline__ uint32_t smem_u32(const void* p) {
    uint32_t a;
    asm("{ .reg .u64 t; cvta.to.shared.u64 t, %1; cvt.u32.u64 %0, t; }" : "=r"(a) : "l"(p));
    return a;
}

#define LDSM_X4(r0, r1, r2, r3, a) \
    asm volatile("ldmatrix.sync.aligned.m8n8.x4.shared.b16 {%0,%1,%2,%3}, [%4];" \
                 : "=r"(r0), "=r"(r1), "=r"(r2), "=r"(r3) : "r"(a))

#define MMA_BF16(d, a0, a1, a2, a3, b0, b1) \
    asm volatile("mma.sync.aligned.m16n8k16.row.col.f32.bf16.bf16.f32 " \
                 "{%0,%1,%2,%3}, {%4,%5,%6,%7}, {%8,%9}, {%0,%1,%2,%3};" \
                 : "+f"((d)[0]), "+f"((d)[1]), "+f"((d)[2]), "+f"((d)[3]) \
                 : "r"(a0), "r"(a1), "r"(a2), "r"(a3), "r"(b0), "r"(b1))

#define CP_ASYNC16(sa, ga, sz) \
    asm volatile("cp.async.cg.shared.global [%0], [%1], 16, %2;" :: "r"(sa), "l"(ga), "r"(sz))
#define CP_COMMIT() asm volatile("cp.async.commit_group;" ::: "memory")
#define CP_WAIT1()  asm volatile("cp.async.wait_group 1;" ::: "memory")
#define CP_WAIT0()  asm volatile("cp.async.wait_group 0;" ::: "memory")

// ---------------- fp32 -> bf16 hi/lo split ----------------
__device__ __forceinline__ void split_bf16(float x, unsigned short& hi, unsigned short& lo) {
    __nv_bfloat16 h = __float2bfloat16(x);
    __nv_bfloat16 l = __float2bfloat16(x - __bfloat162float(h));
    hi = __bfloat16_as_ushort(h);
    lo = __bfloat16_as_ushort(l);
}

__global__ __launch_bounds__(256)
void convert_x_kernel(const float* __restrict__ X) {
    size_t i = (size_t)blockIdx.x * blockDim.x + threadIdx.x;
    const size_t n4 = (size_t)NNODES * DFEAT / 4;
    if (i >= n4) return;
    float4 v = ((const float4*)X)[i];
    unsigned short h0, h1, h2, h3, l0, l1, l2, l3;
    split_bf16(v.x, h0, l0); split_bf16(v.y, h1, l1);
    split_bf16(v.z, h2, l2); split_bf16(v.w, h3, l3);
    uint2 wh = make_uint2((uint32_t)h0 | ((uint32_t)h1 << 16), (uint32_t)h2 | ((uint32_t)h3 << 16));
    uint2 wl = make_uint2((uint32_t)l0 | ((uint32_t)l1 << 16), (uint32_t)l2 | ((uint32_t)l3 << 16));
    *(uint2*)(g_xhi + i * 4) = wh;
    *(uint2*)(g_xlo + i * 4) = wl;
}

__global__ __launch_bounds__(256)
void convert_w_kernel(const float* __restrict__ W1) {
    __shared__ float tile[32][33];
    const int k0 = blockIdx.x * 32;
    const int n0 = blockIdx.y * 32;
    const int tx = threadIdx.x, ty = threadIdx.y;   // 32 x 8
    const int roff = (n0 >= DHID) ? DFEAT : 0;
#pragma unroll
    for (int j = 0; j < 32; j += 8) {
        int k = k0 + ty + j;
        int n = n0 + tx;
        tile[ty + j][tx] = W1[(size_t)(roff + k) * DHID + (n & (DHID - 1))];
    }
    __syncthreads();
#pragma unroll
    for (int j = 0; j < 32; j += 8) {
        int n = n0 + ty + j;
        int k = k0 + tx;
        unsigned short hi, lo;
        split_bf16(tile[tx][ty + j], hi, lo);
        g_bhi[(size_t)n * DFEAT + k] = __ushort_as_bfloat16(hi);
        g_blo[(size_t)n * DFEAT + k] = __ushort_as_bfloat16(lo);
    }
}

// ---------------- HMMA split-bf16 GEMM: g_uv = X @ [W1_top | W1_bot] ----------------
// CTA tile 128x256, BK=32, 8 warps (2m x 4n), warp tile 64x64, 3-stage cp.async.
#define BM 128
#define BN 256
#define BK 32
#define PITCH 80                        // 5 x 16B rows: conflict-free ldmatrix, no swizzle
#define A_TILE_B (BM * PITCH)           // 10240
#define B_TILE_B (BN * PITCH)           // 20480
#define OFF_AHI 0
#define OFF_ALO A_TILE_B
#define OFF_BHI (2 * A_TILE_B)
#define OFF_BLO (2 * A_TILE_B + B_TILE_B)
#define STAGE_B (2 * A_TILE_B + 2 * B_TILE_B)   // 61440
#define NSTAGE 3
#define SMEM_DYN (NSTAGE * STAGE_B)             // 184320

__global__ __launch_bounds__(256, 1)
void gemm_mma_kernel() {
    extern __shared__ char smem[];
    const uint32_t sbase = smem_u32(smem);
    const int tid = threadIdx.x;
    const int wid = tid >> 5, lane = tid & 31;
    const int col0 = blockIdx.x * BN;
    const int row0 = blockIdx.y * BM;
    const int warp_m = wid >> 2;        // 0..1  (64-row slabs)
    const int warp_n = wid & 3;         // 0..3  (64-col slabs)

    float acc[4][8][4];
#pragma unroll
    for (int mi = 0; mi < 4; mi++)
#pragma unroll
        for (int ni = 0; ni < 8; ni++)
#pragma unroll
            for (int q = 0; q < 4; q++) acc[mi][ni][q] = 0.f;

    // --- stage fill: per thread 12 x cp.async (A:2+2 rows, B:4+4 rows) ---
    const int fr  = tid >> 2;           // 0..63
    const int fc  = tid & 3;            // 16B chunk in 64B row
    auto issue_stage = [&](int kt, int slot) {
        const int k0 = kt * BK;
        const uint32_t sb = sbase + slot * STAGE_B;
#pragma unroll
        for (int h = 0; h < 2; h++) {
            const int r = fr + h * 64;
            const size_t goff = (size_t)(row0 + r) * DFEAT + k0 + fc * 8;
            const int sz = (row0 + r < NNODES) ? 16 : 0;
            const uint32_t so = (uint32_t)(r * PITCH + fc * 16);
            CP_ASYNC16(sb + OFF_AHI + so, g_xhi + goff, sz);
            CP_ASYNC16(sb + OFF_ALO + so, g_xlo + goff, sz);
        }
#pragma unroll
        for (int h = 0; h < 4; h++) {
            const int r = fr + h * 64;
            const size_t goff = (size_t)(col0 + r) * DFEAT + k0 + fc * 8;
            const uint32_t so = (uint32_t)(r * PITCH + fc * 16);
            CP_ASYNC16(sb + OFF_BHI + so, g_bhi + goff, 16);
            CP_ASYNC16(sb + OFF_BLO + so, g_blo + goff, 16);
        }
        CP_COMMIT();
    };

    // ldmatrix base offsets (stage-relative)
    const uint32_t a_off = (uint32_t)((warp_m * 64 + (lane & 15)) * PITCH + (lane >> 4) * 16);
    const int grp = lane >> 3, r8 = lane & 7;
    const uint32_t b_off = (uint32_t)((warp_n * 64 + ((grp & 2) ? 8 : 0) + r8) * PITCH
                                      + ((grp & 1) ? 16 : 0));

    issue_stage(0, 0);
    issue_stage(1, 1);

    const int KT = DFEAT / BK;          // 16
    for (int kt = 0; kt < KT; kt++) {
        CP_WAIT1();
        __syncthreads();
        if (kt + 2 < KT) issue_stage(kt + 2, (kt + 2) % NSTAGE);

        const uint32_t sb = sbase + (kt % NSTAGE) * STAGE_B;
#pragma unroll
        for (int ks = 0; ks < 2; ks++) {
            const uint32_t kb = ks * 32;
            uint32_t ah[4][4], al[4][4];
#pragma unroll
            for (int mi = 0; mi < 4; mi++) {
                uint32_t aa = sb + a_off + mi * (16 * PITCH) + kb;
                LDSM_X4(ah[mi][0], ah[mi][1], ah[mi][2], ah[mi][3], aa + OFF_AHI);
                LDSM_X4(al[mi][0], al[mi][1], al[mi][2], al[mi][3], aa + OFF_ALO);
            }
#pragma unroll
            for (int p = 0; p < 4; p++) {           // n-subtile pairs
                uint32_t bh[4], bl[4];
                uint32_t ba = sb + b_off + p * (16 * PITCH) + kb;
                LDSM_X4(bh[0], bh[1], bh[2], bh[3], ba + OFF_BHI);
                LDSM_X4(bl[0], bl[1], bl[2], bl[3], ba + OFF_BLO);
#pragma unroll
                for (int mi = 0; mi < 4; mi++) {
#pragma unroll
                    for (int q = 0; q < 2; q++) {
                        float* d = acc[mi][2 * p + q];
                        MMA_BF16(d, ah[mi][0], ah[mi][1], ah[mi][2], ah[mi][3], bh[2 * q], bh[2 * q + 1]);
                        MMA_BF16(d, ah[mi][0], ah[mi][1], ah[mi][2], ah[mi][3], bl[2 * q], bl[2 * q + 1]);
                        MMA_BF16(d, al[mi][0], al[mi][1], al[mi][2], al[mi][3], bh[2 * q], bh[2 * q + 1]);
                    }
                }
            }
        }
        __syncthreads();
    }
    CP_WAIT0();

    // --- epilogue ---
    const int r_lo = lane >> 2;
    const int c_lo = (lane & 3) * 2;
#pragma unroll
    for (int mi = 0; mi < 4; mi++) {
        const int row_a = row0 + warp_m * 64 + mi * 16 + r_lo;
        const int row_b = row_a + 8;
#pragma unroll
        for (int ni = 0; ni < 8; ni++) {
            const int col = col0 + warp_n * 64 + ni * 8 + c_lo;
            if (row_a < NNODES)
                *(float2*)(g_uv + (size_t)row_a * NCOLS + col) = make_float2(acc[mi][ni][0], acc[mi][ni][1]);
            if (row_b < NNODES)
                *(float2*)(g_uv + (size_t)row_b * NCOLS + col) = make_float2(acc[mi][ni][2], acc[mi][ni][3]);
        }
    }
}

// ---------------- per-edge: out[e] = relu(u[src] + v[dst] + b1) . W2 + b2 ----------------
__global__ __launch_bounds__(256)
void edge_kernel(const void* __restrict__ srcp, const void* __restrict__ dstp,
                 const float* __restrict__ b1, const float* __restrict__ W2,
                 const float* __restrict__ b2, float* __restrict__ out, int E) {
    __shared__ int s_is64;
    __shared__ float warp_s[8];
    const int t = threadIdx.x;
    const int e = blockIdx.x;

    if (t == 0) {
        const int* ps = (const int*)srcp;
        const int* pd = (const int*)dstp;
        int orv = 0;
#pragma unroll
        for (int i = 1; i < 16; i += 2) orv |= ps[i] | pd[i];
        s_is64 = (orv == 0) ? 1 : 0;
    }
    __syncthreads();

    long long s, d;
    if (s_is64) {
        s = ((const long long*)srcp)[e];
        d = ((const long long*)dstp)[e];
    } else {
        s = (long long)((const int*)srcp)[e];
        d = (long long)((const int*)dstp)[e];
    }

    const float4* u4 = (const float4*)(g_uv + (size_t)s * NCOLS);
    const float4* v4 = (const float4*)(g_uv + (size_t)d * NCOLS + DHID);
    float4 u  = u4[t];
    float4 v  = v4[t];
    float4 bb = ((const float4*)b1)[t];
    float4 w  = ((const float4*)W2)[t];

    float acc = fmaxf(u.x + v.x + bb.x, 0.f) * w.x
              + fmaxf(u.y + v.y + bb.y, 0.f) * w.y
              + fmaxf(u.z + v.z + bb.z, 0.f) * w.z
              + fmaxf(u.w + v.w + bb.w, 0.f) * w.w;

#pragma unroll
    for (int o = 16; o > 0; o >>= 1) acc += __shfl_xor_sync(0xffffffffu, acc, o);
    if ((t & 31) == 0) warp_s[t >> 5] = acc;
    __syncthreads();
    if (t < 8) {
        float a = warp_s[t];
#pragma unroll
        for (int o = 4; o > 0; o >>= 1) a += __shfl_xor_sync(0xffu, a, o);
        if (t == 0) out[e] = a + b2[0];
    }
}

extern "C" void kernel_launch(void* const* d_in, const int* in_sizes, int n_in,
                              void* d_out, int out_size) {
    const float* x   = (const float*)d_in[0];
    const void*  src = d_in[1];
    const void*  dst = d_in[2];
    const float* W1  = (const float*)d_in[3];
    const float* b1  = (const float*)d_in[4];
    const float* W2  = (const float*)d_in[5];
    const float* b2  = (const float*)d_in[6];
    float* out = (float*)d_out;
    const int E = in_sizes[1];

    cudaFuncSetAttribute(gemm_mma_kernel, cudaFuncAttributeMaxDynamicSharedMemorySize, SMEM_DYN);

    const size_t n4 = (size_t)NNODES * DFEAT / 4;
    convert_x_kernel<<<(unsigned)((n4 + 255) / 256), 256>>>(x);
    convert_w_kernel<<<dim3(DFEAT / 32, NCOLS / 32), dim3(32, 8)>>>(W1);
    gemm_mma_kernel<<<dim3(NCOLS / BN, (NNODES + BM - 1) / BM), 256, SMEM_DYN>>>();
    edge_kernel<<<E, 256>>>(src, dst, b1, W2, b2, out, E);
}

// round 5
// speedup vs baseline: 1.1382x; 1.1382x over previous
#include <cuda_runtime.h>
#include <cuda_bf16.h>
#include <cstdint>

#define NNODES 50000
#define DFEAT  512
#define DHID   1024
#define NCOLS  2048

// ---------------- device scratch ----------------
__device__ __align__(16) float g_uv[(size_t)NNODES * NCOLS];          // node GEMM output [N, 2048]
__device__ __align__(16) __nv_bfloat16 g_xhi[(size_t)NNODES * DFEAT];
__device__ __align__(16) __nv_bfloat16 g_xlo[(size_t)NNODES * DFEAT];
__device__ __align__(16) __nv_bfloat16 g_bhi[(size_t)NCOLS * DFEAT];  // W1^T hi [2048][512]
__device__ __align__(16) __nv_bfloat16 g_blo[(size_t)NCOLS * DFEAT];

__device__ __forceinline__ uint32_t smem_u32(const void* p) {
    uint32_t a;
    asm("{ .reg .u64 t; cvta.to.shared.u64 t, %1; cvt.u32.u64 %0, t; }" : "=r"(a) : "l"(p));
    return a;
}

#define LDSM_X4(r0, r1, r2, r3, a) \
    asm volatile("ldmatrix.sync.aligned.m8n8.x4.shared.b16 {%0,%1,%2,%3}, [%4];" \
                 : "=r"(r0), "=r"(r1), "=r"(r2), "=r"(r3) : "r"(a))

#define MMA_BF16(d, a, b) \
    asm volatile("mma.sync.aligned.m16n8k16.row.col.f32.bf16.bf16.f32 " \
                 "{%0,%1,%2,%3}, {%4,%5,%6,%7}, {%8,%9}, {%0,%1,%2,%3};" \
                 : "+f"((d)[0]), "+f"((d)[1]), "+f"((d)[2]), "+f"((d)[3]) \
                 : "r"((a)[0]), "r"((a)[1]), "r"((a)[2]), "r"((a)[3]), "r"((b)[0]), "r"((b)[1]))

#define CP_ASYNC16(sa, ga, sz) \
    asm volatile("cp.async.cg.shared.global [%0], [%1], 16, %2;" :: "r"(sa), "l"(ga), "r"(sz))
#define CP_COMMIT() asm volatile("cp.async.commit_group;" ::: "memory")
#define CP_WAIT(n)  asm volatile("cp.async.wait_group %0;" :: "n"(n) : "memory")

// ---------------- fp32 -> bf16 hi/lo split ----------------
__device__ __forceinline__ void split_bf16(float x, unsigned short& hi, unsigned short& lo) {
    __nv_bfloat16 h = __float2bfloat16(x);
    __nv_bfloat16 l = __float2bfloat16(x - __bfloat162float(h));
    hi = __bfloat16_as_ushort(h);
    lo = __bfloat16_as_ushort(l);
}

__global__ __launch_bounds__(256)
void convert_x_kernel(const float* __restrict__ X) {
    size_t i = (size_t)blockIdx.x * blockDim.x + threadIdx.x;   // float4 index
    const size_t n4 = (size_t)NNODES * DFEAT / 4;
    if (i >= n4) return;
    float4 v = ((const float4*)X)[i];
    unsigned short h0, h1, h2, h3, l0, l1, l2, l3;
    split_bf16(v.x, h0, l0); split_bf16(v.y, h1, l1);
    split_bf16(v.z, h2, l2); split_bf16(v.w, h3, l3);
    uint2 wh = make_uint2((uint32_t)h0 | ((uint32_t)h1 << 16), (uint32_t)h2 | ((uint32_t)h3 << 16));
    uint2 wl = make_uint2((uint32_t)l0 | ((uint32_t)l1 << 16), (uint32_t)l2 | ((uint32_t)l3 << 16));
    *(uint2*)(g_xhi + i * 4) = wh;
    *(uint2*)(g_xlo + i * 4) = wl;
}

__global__ __launch_bounds__(256)
void convert_w_kernel(const float* __restrict__ W1) {
    __shared__ float tile[32][33];
    const int k0 = blockIdx.x * 32;     // k in [0,512)
    const int n0 = blockIdx.y * 32;     // n in [0,2048)
    const int tx = threadIdx.x, ty = threadIdx.y;   // 32 x 8
    const int roff = (n0 >= DHID) ? DFEAT : 0;
#pragma unroll
    for (int j = 0; j < 32; j += 8) {
        int k = k0 + ty + j;
        int n = n0 + tx;
        tile[ty + j][tx] = W1[(size_t)(roff + k) * DHID + (n & (DHID - 1))];
    }
    __syncthreads();
#pragma unroll
    for (int j = 0; j < 32; j += 8) {
        int n = n0 + ty + j;
        int k = k0 + tx;
        unsigned short hi, lo;
        split_bf16(tile[tx][ty + j], hi, lo);
        g_bhi[(size_t)n * DFEAT + k] = __ushort_as_bfloat16(hi);
        g_blo[(size_t)n * DFEAT + k] = __ushort_as_bfloat16(lo);
    }
}

// ---------------- HMMA split-bf16 GEMM: g_uv = X @ [W1_top | W1_bot] (+b1 on u-half) ----
#define BM 128
#define BN 128
#define BK 32
#define PITCH 80                        // 5 x 16B: conflict-free ldmatrix, no swizzle
#define TILE_B (128 * PITCH)            // 10240 B
#define STAGE_B (4 * TILE_B)            // Ahi, Alo, Bhi, Blo = 40960 B
#define SMEM_DYN (2 * STAGE_B)          // 81920 B double-buffered

__global__ __launch_bounds__(256)
void gemm_mma_kernel(const float* __restrict__ b1) {
    extern __shared__ char smem[];
    const uint32_t sbase = smem_u32(smem);
    const int tid = threadIdx.x;
    const int wid = tid >> 5, lane = tid & 31;
    const int col0 = blockIdx.x * BN;
    const int row0 = blockIdx.y * BM;
    const int warp_m = wid & 3;         // 4 m-warps of 32 rows
    const int warp_n = wid >> 2;        // 2 n-warps of 64 cols

    float acc[2][8][4];
#pragma unroll
    for (int mi = 0; mi < 2; mi++)
#pragma unroll
        for (int ni = 0; ni < 8; ni++)
#pragma unroll
            for (int q = 0; q < 4; q++) acc[mi][ni][q] = 0.f;

    const int lr = tid >> 2;
    const int lc4 = tid & 3;
    auto issue_stage = [&](int kt, int s) {
        const int k0 = kt * BK;
        const uint32_t sb = sbase + s * STAGE_B;
#pragma unroll
        for (int j = 0; j < 8; j++) {
            const int tile = j >> 1;
            const int r = lr + (j & 1) * 64;
            const uint32_t sa = sb + tile * TILE_B + r * PITCH + lc4 * 16;
            const __nv_bfloat16* g;
            int sz = 16;
            if (tile < 2) {
                g = (tile == 0 ? g_xhi : g_xlo) + (size_t)(row0 + r) * DFEAT + k0 + lc4 * 8;
                if (row0 + r >= NNODES) sz = 0;
            } else {
                g = (tile == 2 ? g_bhi : g_blo) + (size_t)(col0 + r) * DFEAT + k0 + lc4 * 8;
            }
            CP_ASYNC16(sa, g, sz);
        }
        CP_COMMIT();
    };

    const uint32_t a_off = (uint32_t)((warp_m * 32 + (lane & 15)) * PITCH + (lane >> 4) * 16);
    const int grp = lane >> 3, r8 = lane & 7;
    const uint32_t b_off = (uint32_t)((warp_n * 64 + ((grp & 2) ? 8 : 0) + r8) * PITCH
                                      + ((grp & 1) ? 16 : 0));

    issue_stage(0, 0);

    const int KT = DFEAT / BK;          // 16
    for (int kt = 0; kt < KT; kt++) {
        const int cur = kt & 1;
        if (kt + 1 < KT) { issue_stage(kt + 1, cur ^ 1); CP_WAIT(1); }
        else            { CP_WAIT(0); }
        __syncthreads();

        const uint32_t sb = sbase + cur * STAGE_B;
#pragma unroll
        for (int ks = 0; ks < 2; ks++) {
            const uint32_t kb = ks * 32;
            uint32_t ah[2][4], al[2][4], bh[8][2], bl[8][2];
#pragma unroll
            for (int mi = 0; mi < 2; mi++) {
                uint32_t aa = sb + a_off + mi * (16 * PITCH) + kb;
                LDSM_X4(ah[mi][0], ah[mi][1], ah[mi][2], ah[mi][3], aa);
                LDSM_X4(al[mi][0], al[mi][1], al[mi][2], al[mi][3], aa + TILE_B);
            }
#pragma unroll
            for (int p = 0; p < 4; p++) {
                uint32_t ba = sb + 2 * TILE_B + b_off + p * (16 * PITCH) + kb;
                LDSM_X4(bh[2 * p][0], bh[2 * p][1], bh[2 * p + 1][0], bh[2 * p + 1][1], ba);
                LDSM_X4(bl[2 * p][0], bl[2 * p][1], bl[2 * p + 1][0], bl[2 * p + 1][1], ba + TILE_B);
            }
#pragma unroll
            for (int mi = 0; mi < 2; mi++)
#pragma unroll
                for (int ni = 0; ni < 8; ni++) {
                    MMA_BF16(acc[mi][ni], ah[mi], bh[ni]);
                    MMA_BF16(acc[mi][ni], ah[mi], bl[ni]);
                    MMA_BF16(acc[mi][ni], al[mi], bh[ni]);
                }
        }
        __syncthreads();
    }

    // --- epilogue: add b1 to the u-half (cols < DHID), write g_uv
    const int r_lo = lane >> 2;
    const int c_lo = (lane & 3) * 2;
#pragma unroll
    for (int mi = 0; mi < 2; mi++) {
        const int row_a = row0 + warp_m * 32 + mi * 16 + r_lo;
        const int row_b = row_a + 8;
#pragma unroll
        for (int ni = 0; ni < 8; ni++) {
            const int col = col0 + warp_n * 64 + ni * 8 + c_lo;
            float bx = 0.f, by = 0.f;
            if (col < DHID) { bx = __ldg(b1 + col); by = __ldg(b1 + col + 1); }
            if (row_a < NNODES)
                *(float2*)(g_uv + (size_t)row_a * NCOLS + col) =
                    make_float2(acc[mi][ni][0] + bx, acc[mi][ni][1] + by);
            if (row_b < NNODES)
                *(float2*)(g_uv + (size_t)row_b * NCOLS + col) =
                    make_float2(acc[mi][ni][2] + bx, acc[mi][ni][3] + by);
        }
    }
}

// ---------------- per-edge: out[e] = relu(u'[src] + v[dst]) . W2 + b2  (b1 folded into u')
// One warp per edge, 8 edges per 256-thread block. Pure shuffle reduce, no barriers.
__global__ __launch_bounds__(256)
void edge_kernel(const void* __restrict__ srcp, const void* __restrict__ dstp,
                 const float* __restrict__ W2, const float* __restrict__ b2,
                 float* __restrict__ out, int E) {
    __shared__ int s_is64;
    if (threadIdx.x == 0) {
        const int* ps = (const int*)srcp;
        const int* pd = (const int*)dstp;
        int orv = 0;
#pragma unroll
        for (int i = 1; i < 16; i += 2) orv |= ps[i] | pd[i];
        s_is64 = (orv == 0) ? 1 : 0;
    }
    __syncthreads();

    const int wid  = threadIdx.x >> 5;
    const int lane = threadIdx.x & 31;
    const int e = blockIdx.x * 8 + wid;
    if (e >= E) return;

    long long s, d;
    if (s_is64) {
        s = ((const long long*)srcp)[e];
        d = ((const long long*)dstp)[e];
    } else {
        s = (long long)((const int*)srcp)[e];
        d = (long long)((const int*)dstp)[e];
    }

    const float4* __restrict__ U = (const float4*)(g_uv + (size_t)s * NCOLS);
    const float4* __restrict__ V = (const float4*)(g_uv + (size_t)d * NCOLS + DHID);
    const float4* __restrict__ W = (const float4*)W2;

    float acc = 0.f;
#pragma unroll
    for (int i = 0; i < 8; i++) {
        const int c = i * 32 + lane;
        float4 u = U[c];
        float4 v = V[c];
        float4 w = W[c];
        acc += fmaxf(u.x + v.x, 0.f) * w.x
             + fmaxf(u.y + v.y, 0.f) * w.y
             + fmaxf(u.z + v.z, 0.f) * w.z
             + fmaxf(u.w + v.w, 0.f) * w.w;
    }
#pragma unroll
    for (int o = 16; o > 0; o >>= 1) acc += __shfl_xor_sync(0xffffffffu, acc, o);
    if (lane == 0) out[e] = acc + b2[0];
}

extern "C" void kernel_launch(void* const* d_in, const int* in_sizes, int n_in,
                              void* d_out, int out_size) {
    const float* x   = (const float*)d_in[0];
    const void*  src = d_in[1];
    const void*  dst = d_in[2];
    const float* W1  = (const float*)d_in[3];
    const float* b1  = (const float*)d_in[4];
    const float* W2  = (const float*)d_in[5];
    const float* b2  = (const float*)d_in[6];
    float* out = (float*)d_out;
    const int E = in_sizes[1];

    cudaFuncSetAttribute(gemm_mma_kernel, cudaFuncAttributeMaxDynamicSharedMemorySize, SMEM_DYN);

    const size_t n4 = (size_t)NNODES * DFEAT / 4;
    convert_x_kernel<<<(unsigned)((n4 + 255) / 256), 256>>>(x);
    convert_w_kernel<<<dim3(DFEAT / 32, NCOLS / 32), dim3(32, 8)>>>(W1);
    gemm_mma_kernel<<<dim3(NCOLS / BN, (NNODES + BM - 1) / BM), 256, SMEM_DYN>>>(b1);
    edge_kernel<<<(E + 7) / 8, 256>>>(src, dst, W2, b2, out, E);
}

// round 6
// speedup vs baseline: 1.4908x; 1.3099x over previous
#include <cuda_runtime.h>
#include <cuda_fp16.h>
#include <cstdint>

#define NNODES 50000
#define DFEAT  512
#define DHID   1024
#define NCOLS  2048

// ---------------- device scratch ----------------
__device__ __align__(16) float g_uv[(size_t)NNODES * NCOLS];     // node GEMM output [N, 2048]
__device__ __align__(16) __half g_xh[(size_t)NNODES * DFEAT];    // X hi (fp16)
__device__ __align__(16) __half g_xl[(size_t)NNODES * DFEAT];    // X lo (fp16 residual)
__device__ __align__(16) __half g_bh[(size_t)NCOLS * DFEAT];     // W1^T fp16 [2048][512]

__device__ __forceinline__ uint32_t smem_u32(const void* p) {
    uint32_t a;
    asm("{ .reg .u64 t; cvta.to.shared.u64 t, %1; cvt.u32.u64 %0, t; }" : "=r"(a) : "l"(p));
    return a;
}

#define LDSM_X4(r0, r1, r2, r3, a) \
    asm volatile("ldmatrix.sync.aligned.m8n8.x4.shared.b16 {%0,%1,%2,%3}, [%4];" \
                 : "=r"(r0), "=r"(r1), "=r"(r2), "=r"(r3) : "r"(a))

#define MMA_F16(d, a, b) \
    asm volatile("mma.sync.aligned.m16n8k16.row.col.f32.f16.f16.f32 " \
                 "{%0,%1,%2,%3}, {%4,%5,%6,%7}, {%8,%9}, {%0,%1,%2,%3};" \
                 : "+f"((d)[0]), "+f"((d)[1]), "+f"((d)[2]), "+f"((d)[3]) \
                 : "r"((a)[0]), "r"((a)[1]), "r"((a)[2]), "r"((a)[3]), "r"((b)[0]), "r"((b)[1]))

#define CP_ASYNC16(sa, ga, sz) \
    asm volatile("cp.async.cg.shared.global [%0], [%1], 16, %2;" :: "r"(sa), "l"(ga), "r"(sz))
#define CP_COMMIT() asm volatile("cp.async.commit_group;" ::: "memory")
#define CP_WAIT1()  asm volatile("cp.async.wait_group 1;" ::: "memory")
#define CP_WAIT0()  asm volatile("cp.async.wait_group 0;" ::: "memory")

// ---------------- fp32 -> fp16 hi/lo split of X ----------------
__device__ __forceinline__ void split_f16(float x, unsigned short& hi, unsigned short& lo) {
    __half h = __float2half_rn(x);
    __half l = __float2half_rn(x - __half2float(h));
    hi = __half_as_ushort(h);
    lo = __half_as_ushort(l);
}

__global__ __launch_bounds__(256)
void convert_x_kernel(const float* __restrict__ X) {
    size_t i = (size_t)blockIdx.x * blockDim.x + threadIdx.x;   // float4 index
    const size_t n4 = (size_t)NNODES * DFEAT / 4;
    if (i >= n4) return;
    float4 v = ((const float4*)X)[i];
    unsigned short h0, h1, h2, h3, l0, l1, l2, l3;
    split_f16(v.x, h0, l0); split_f16(v.y, h1, l1);
    split_f16(v.z, h2, l2); split_f16(v.w, h3, l3);
    uint2 wh = make_uint2((uint32_t)h0 | ((uint32_t)h1 << 16), (uint32_t)h2 | ((uint32_t)h3 << 16));
    uint2 wl = make_uint2((uint32_t)l0 | ((uint32_t)l1 << 16), (uint32_t)l2 | ((uint32_t)l3 << 16));
    *(uint2*)(g_xh + i * 4) = wh;
    *(uint2*)(g_xl + i * 4) = wl;
}

// W1^T fp16:  g_bh[n][k] = W1[half(n)*512 + k][n & 1023]
__global__ __launch_bounds__(256)
void convert_w_kernel(const float* __restrict__ W1) {
    __shared__ float tile[32][33];
    const int k0 = blockIdx.x * 32;     // k in [0,512)
    const int n0 = blockIdx.y * 32;     // n in [0,2048)
    const int tx = threadIdx.x, ty = threadIdx.y;   // 32 x 8
    const int roff = (n0 >= DHID) ? DFEAT : 0;
#pragma unroll
    for (int j = 0; j < 32; j += 8) {
        int k = k0 + ty + j;
        int n = n0 + tx;
        tile[ty + j][tx] = W1[(size_t)(roff + k) * DHID + (n & (DHID - 1))];
    }
    __syncthreads();
#pragma unroll
    for (int j = 0; j < 32; j += 8) {
        int n = n0 + ty + j;
        int k = k0 + tx;
        g_bh[(size_t)n * DFEAT + k] = __float2half_rn(tile[tx][ty + j]);
    }
}

// ---------------- HMMA 2-pass fp16 GEMM: g_uv = X @ [W1_top | W1_bot] (+b1 on u-half) ----
// CTA 128x128, BK=32, 8 warps (4m x 2n), warp tile 32x64, 3-stage cp.async.
#define BM 128
#define BN 128
#define BK 32
#define PITCH 80                        // 5 x 16B: conflict-free ldmatrix, no swizzle
#define TILE_B (128 * PITCH)            // 10240 B
#define OFF_AH 0
#define OFF_AL TILE_B
#define OFF_BH (2 * TILE_B)
#define STAGE_B (3 * TILE_B)            // 30720 B
#define NSTAGE 3
#define SMEM_DYN (NSTAGE * STAGE_B)     // 92160 B

__global__ __launch_bounds__(256, 2)
void gemm_mma_kernel(const float* __restrict__ b1) {
    extern __shared__ char smem[];
    const uint32_t sbase = smem_u32(smem);
    const int tid = threadIdx.x;
    const int wid = tid >> 5, lane = tid & 31;
    const int col0 = blockIdx.x * BN;
    const int row0 = blockIdx.y * BM;
    const int warp_m = wid & 3;         // 4 m-warps of 32 rows
    const int warp_n = wid >> 2;        // 2 n-warps of 64 cols

    float acc[2][8][4];
#pragma unroll
    for (int mi = 0; mi < 2; mi++)
#pragma unroll
        for (int ni = 0; ni < 8; ni++)
#pragma unroll
            for (int q = 0; q < 4; q++) acc[mi][ni][q] = 0.f;

    // --- stage fill: 3 tiles x 512 chunks -> 6 cp.async / thread
    const int lr  = tid >> 2;           // 0..63
    const int lc4 = tid & 3;
    auto issue_stage = [&](int kt, int slot) {
        const int k0 = kt * BK;
        const uint32_t sb = sbase + slot * STAGE_B;
#pragma unroll
        for (int h = 0; h < 2; h++) {
            const int r = lr + h * 64;
            const uint32_t so = (uint32_t)(r * PITCH + lc4 * 16);
            const size_t aoff = (size_t)(row0 + r) * DFEAT + k0 + lc4 * 8;
            const int sz = (row0 + r < NNODES) ? 16 : 0;
            CP_ASYNC16(sb + OFF_AH + so, g_xh + aoff, sz);
            CP_ASYNC16(sb + OFF_AL + so, g_xl + aoff, sz);
            const size_t boff = (size_t)(col0 + r) * DFEAT + k0 + lc4 * 8;
            CP_ASYNC16(sb + OFF_BH + so, g_bh + boff, 16);
        }
        CP_COMMIT();
    };

    const uint32_t a_off = (uint32_t)((warp_m * 32 + (lane & 15)) * PITCH + (lane >> 4) * 16);
    const int grp = lane >> 3, r8 = lane & 7;
    const uint32_t b_off = (uint32_t)((warp_n * 64 + ((grp & 2) ? 8 : 0) + r8) * PITCH
                                      + ((grp & 1) ? 16 : 0));

    issue_stage(0, 0);
    issue_stage(1, 1);

    const int KT = DFEAT / BK;          // 16
    for (int kt = 0; kt < KT; kt++) {
        if (kt + 2 < KT) CP_WAIT1(); else CP_WAIT0();
        __syncthreads();
        if (kt + 2 < KT) issue_stage(kt + 2, (kt + 2) % NSTAGE);

        const uint32_t sb = sbase + (kt % NSTAGE) * STAGE_B;
#pragma unroll
        for (int ks = 0; ks < 2; ks++) {
            const uint32_t kb = ks * 32;
            uint32_t ah[2][4], al[2][4], bh[8][2];
#pragma unroll
            for (int mi = 0; mi < 2; mi++) {
                uint32_t aa = sb + a_off + mi * (16 * PITCH) + kb;
                LDSM_X4(ah[mi][0], ah[mi][1], ah[mi][2], ah[mi][3], aa + OFF_AH);
                LDSM_X4(al[mi][0], al[mi][1], al[mi][2], al[mi][3], aa + OFF_AL);
            }
#pragma unroll
            for (int p = 0; p < 4; p++) {
                uint32_t ba = sb + OFF_BH + b_off + p * (16 * PITCH) + kb;
                LDSM_X4(bh[2 * p][0], bh[2 * p][1], bh[2 * p + 1][0], bh[2 * p + 1][1], ba);
            }
#pragma unroll
            for (int mi = 0; mi < 2; mi++)
#pragma unroll
                for (int ni = 0; ni < 8; ni++) {
                    MMA_F16(acc[mi][ni], ah[mi], bh[ni]);
                    MMA_F16(acc[mi][ni], al[mi], bh[ni]);
                }
        }
        __syncthreads();
    }

    // --- epilogue: add b1 to the u-half (cols < DHID), write g_uv
    const int r_lo = lane >> 2;
    const int c_lo = (lane & 3) * 2;
#pragma unroll
    for (int mi = 0; mi < 2; mi++) {
        const int row_a = row0 + warp_m * 32 + mi * 16 + r_lo;
        const int row_b = row_a + 8;
#pragma unroll
        for (int ni = 0; ni < 8; ni++) {
            const int col = col0 + warp_n * 64 + ni * 8 + c_lo;
            float bx = 0.f, by = 0.f;
            if (col < DHID) { bx = __ldg(b1 + col); by = __ldg(b1 + col + 1); }
            if (row_a < NNODES)
                *(float2*)(g_uv + (size_t)row_a * NCOLS + col) =
                    make_float2(acc[mi][ni][0] + bx, acc[mi][ni][1] + by);
            if (row_b < NNODES)
                *(float2*)(g_uv + (size_t)row_b * NCOLS + col) =
                    make_float2(acc[mi][ni][2] + bx, acc[mi][ni][3] + by);
        }
    }
}

// ---------------- per-edge: out[e] = relu(u'[src] + v[dst]) . W2 + b2  (b1 folded into u')
__global__ __launch_bounds__(256)
void edge_kernel(const void* __restrict__ srcp, const void* __restrict__ dstp,
                 const float* __restrict__ W2, const float* __restrict__ b2,
                 float* __restrict__ out, int E) {
    __shared__ int s_is64;
    if (threadIdx.x == 0) {
        const int* ps = (const int*)srcp;
        const int* pd = (const int*)dstp;
        int orv = 0;
#pragma unroll
        for (int i = 1; i < 16; i += 2) orv |= ps[i] | pd[i];
        s_is64 = (orv == 0) ? 1 : 0;
    }
    __syncthreads();

    const int wid  = threadIdx.x >> 5;
    const int lane = threadIdx.x & 31;
    const int e = blockIdx.x * 8 + wid;
    if (e >= E) return;

    long long s, d;
    if (s_is64) {
        s = ((const long long*)srcp)[e];
        d = ((const long long*)dstp)[e];
    } else {
        s = (long long)((const int*)srcp)[e];
        d = (long long)((const int*)dstp)[e];
    }

    const float4* __restrict__ U = (const float4*)(g_uv + (size_t)s * NCOLS);
    const float4* __restrict__ V = (const float4*)(g_uv + (size_t)d * NCOLS + DHID);
    const float4* __restrict__ W = (const float4*)W2;

    float acc = 0.f;
#pragma unroll
    for (int i = 0; i < 8; i++) {
        const int c = i * 32 + lane;
        float4 u = U[c];
        float4 v = V[c];
        float4 w = W[c];
        acc += fmaxf(u.x + v.x, 0.f) * w.x
             + fmaxf(u.y + v.y, 0.f) * w.y
             + fmaxf(u.z + v.z, 0.f) * w.z
             + fmaxf(u.w + v.w, 0.f) * w.w;
    }
#pragma unroll
    for (int o = 16; o > 0; o >>= 1) acc += __shfl_xor_sync(0xffffffffu, acc, o);
    if (lane == 0) out[e] = acc + b2[0];
}

extern "C" void kernel_launch(void* const* d_in, const int* in_sizes, int n_in,
                              void* d_out, int out_size) {
    const float* x   = (const float*)d_in[0];
    const void*  src = d_in[1];
    const void*  dst = d_in[2];
    const float* W1  = (const float*)d_in[3];
    const float* b1  = (const float*)d_in[4];
    const float* W2  = (const float*)d_in[5];
    const float* b2  = (const float*)d_in[6];
    float* out = (float*)d_out;
    const int E = in_sizes[1];

    cudaFuncSetAttribute(gemm_mma_kernel, cudaFuncAttributeMaxDynamicSharedMemorySize, SMEM_DYN);

    const size_t n4 = (size_t)NNODES * DFEAT / 4;
    convert_x_kernel<<<(unsigned)((n4 + 255) / 256), 256>>>(x);
    convert_w_kernel<<<dim3(DFEAT / 32, NCOLS / 32), dim3(32, 8)>>>(W1);
    gemm_mma_kernel<<<dim3(NCOLS / BN, (NNODES + BM - 1) / BM), 256, SMEM_DYN>>>(b1);
    edge_kernel<<<(E + 7) / 8, 256>>>(src, dst, W2, b2, out, E);
}

// round 7
// speedup vs baseline: 2.0628x; 1.3837x over previous
#include <cuda_runtime.h>
#include <cuda_fp16.h>
#include <cstdint>

#define NNODES 50000
#define DFEAT  512
#define DHID   1024
#define NCOLS  2048

// ---------------- device scratch ----------------
__device__ __align__(16) float g_uv[(size_t)NNODES * NCOLS];     // node GEMM output [N, 2048]
__device__ __align__(16) __half g_xh[(size_t)NNODES * DFEAT];    // X fp16
__device__ __align__(16) __half g_bh[(size_t)NCOLS * DFEAT];     // W1^T fp16 [2048][512]

__device__ __forceinline__ uint32_t smem_u32(const void* p) {
    uint32_t a;
    asm("{ .reg .u64 t; cvta.to.shared.u64 t, %1; cvt.u32.u64 %0, t; }" : "=r"(a) : "l"(p));
    return a;
}

#define LDSM_X4(r0, r1, r2, r3, a) \
    asm volatile("ldmatrix.sync.aligned.m8n8.x4.shared.b16 {%0,%1,%2,%3}, [%4];" \
                 : "=r"(r0), "=r"(r1), "=r"(r2), "=r"(r3) : "r"(a))

#define MMA_F16(d, a, b) \
    asm volatile("mma.sync.aligned.m16n8k16.row.col.f32.f16.f16.f32 " \
                 "{%0,%1,%2,%3}, {%4,%5,%6,%7}, {%8,%9}, {%0,%1,%2,%3};" \
                 : "+f"((d)[0]), "+f"((d)[1]), "+f"((d)[2]), "+f"((d)[3]) \
                 : "r"((a)[0]), "r"((a)[1]), "r"((a)[2]), "r"((a)[3]), "r"((b)[0]), "r"((b)[1]))

#define CP_ASYNC16(sa, ga, sz) \
    asm volatile("cp.async.cg.shared.global [%0], [%1], 16, %2;" :: "r"(sa), "l"(ga), "r"(sz))
#define CP_COMMIT() asm volatile("cp.async.commit_group;" ::: "memory")
#define CP_WAIT2()  asm volatile("cp.async.wait_group 2;" ::: "memory")
#define CP_WAIT0()  asm volatile("cp.async.wait_group 0;" ::: "memory")

__global__ __launch_bounds__(256)
void convert_x_kernel(const float* __restrict__ X) {
    size_t i = (size_t)blockIdx.x * blockDim.x + threadIdx.x;   // float4 index
    const size_t n4 = (size_t)NNODES * DFEAT / 4;
    if (i >= n4) return;
    float4 v = ((const float4*)X)[i];
    unsigned short h0 = __half_as_ushort(__float2half_rn(v.x));
    unsigned short h1 = __half_as_ushort(__float2half_rn(v.y));
    unsigned short h2 = __half_as_ushort(__float2half_rn(v.z));
    unsigned short h3 = __half_as_ushort(__float2half_rn(v.w));
    *(uint2*)(g_xh + i * 4) = make_uint2((uint32_t)h0 | ((uint32_t)h1 << 16),
                                         (uint32_t)h2 | ((uint32_t)h3 << 16));
}

// W1^T fp16:  g_bh[n][k] = W1[half(n)*512 + k][n & 1023]
__global__ __launch_bounds__(256)
void convert_w_kernel(const float* __restrict__ W1) {
    __shared__ float tile[32][33];
    const int k0 = blockIdx.x * 32;     // k in [0,512)
    const int n0 = blockIdx.y * 32;     // n in [0,2048)
    const int tx = threadIdx.x, ty = threadIdx.y;   // 32 x 8
    const int roff = (n0 >= DHID) ? DFEAT : 0;
#pragma unroll
    for (int j = 0; j < 32; j += 8) {
        int k = k0 + ty + j;
        int n = n0 + tx;
        tile[ty + j][tx] = W1[(size_t)(roff + k) * DHID + (n & (DHID - 1))];
    }
    __syncthreads();
#pragma unroll
    for (int j = 0; j < 32; j += 8) {
        int n = n0 + ty + j;
        int k = k0 + tx;
        g_bh[(size_t)n * DFEAT + k] = __float2half_rn(tile[tx][ty + j]);
    }
}

// ---------------- HMMA single-pass fp16 GEMM: g_uv = X @ [W1_top | W1_bot] (+b1 on u-half)
// CTA 128x128, BK=32, 8 warps (4m x 2n), warp tile 32x64, 4-stage cp.async.
#define BM 128
#define BN 128
#define BK 32
#define PITCH 80                        // 5 x 16B: conflict-free ldmatrix, no swizzle
#define TILE_B (128 * PITCH)            // 10240 B
#define OFF_AH 0
#define OFF_BH TILE_B
#define STAGE_B (2 * TILE_B)            // 20480 B
#define NSTAGE 4
#define SMEM_DYN (NSTAGE * STAGE_B)     // 81920 B

__global__ __launch_bounds__(256, 2)
void gemm_mma_kernel(const float* __restrict__ b1) {
    extern __shared__ char smem[];
    const uint32_t sbase = smem_u32(smem);
    const int tid = threadIdx.x;
    const int wid = tid >> 5, lane = tid & 31;
    const int col0 = blockIdx.x * BN;
    const int row0 = blockIdx.y * BM;
    const int warp_m = wid & 3;         // 4 m-warps of 32 rows
    const int warp_n = wid >> 2;        // 2 n-warps of 64 cols

    float acc[2][8][4];
#pragma unroll
    for (int mi = 0; mi < 2; mi++)
#pragma unroll
        for (int ni = 0; ni < 8; ni++)
#pragma unroll
            for (int q = 0; q < 4; q++) acc[mi][ni][q] = 0.f;

    // --- stage fill: 2 tiles x 512 chunks -> 4 cp.async / thread
    const int lr  = tid >> 2;           // 0..63
    const int lc4 = tid & 3;
    auto issue_stage = [&](int kt, int slot) {
        const int k0 = kt * BK;
        const uint32_t sb = sbase + slot * STAGE_B;
#pragma unroll
        for (int h = 0; h < 2; h++) {
            const int r = lr + h * 64;
            const uint32_t so = (uint32_t)(r * PITCH + lc4 * 16);
            const size_t aoff = (size_t)(row0 + r) * DFEAT + k0 + lc4 * 8;
            const int sz = (row0 + r < NNODES) ? 16 : 0;
            CP_ASYNC16(sb + OFF_AH + so, g_xh + aoff, sz);
            const size_t boff = (size_t)(col0 + r) * DFEAT + k0 + lc4 * 8;
            CP_ASYNC16(sb + OFF_BH + so, g_bh + boff, 16);
        }
        CP_COMMIT();
    };

    const uint32_t a_off = (uint32_t)((warp_m * 32 + (lane & 15)) * PITCH + (lane >> 4) * 16);
    const int grp = lane >> 3, r8 = lane & 7;
    const uint32_t b_off = (uint32_t)((warp_n * 64 + ((grp & 2) ? 8 : 0) + r8) * PITCH
                                      + ((grp & 1) ? 16 : 0));

    issue_stage(0, 0);
    issue_stage(1, 1);
    issue_stage(2, 2);

    const int KT = DFEAT / BK;          // 16
    for (int kt = 0; kt < KT; kt++) {
        if (kt + 3 < KT) CP_WAIT2(); else CP_WAIT0();
        __syncthreads();
        if (kt + 3 < KT) issue_stage(kt + 3, (kt + 3) % NSTAGE);

        const uint32_t sb = sbase + (kt % NSTAGE) * STAGE_B;
#pragma unroll
        for (int ks = 0; ks < 2; ks++) {
            const uint32_t kb = ks * 32;
            uint32_t ah[2][4], bh[8][2];
#pragma unroll
            for (int mi = 0; mi < 2; mi++) {
                uint32_t aa = sb + a_off + mi * (16 * PITCH) + kb;
                LDSM_X4(ah[mi][0], ah[mi][1], ah[mi][2], ah[mi][3], aa + OFF_AH);
            }
#pragma unroll
            for (int p = 0; p < 4; p++) {
                uint32_t ba = sb + OFF_BH + b_off + p * (16 * PITCH) + kb;
                LDSM_X4(bh[2 * p][0], bh[2 * p][1], bh[2 * p + 1][0], bh[2 * p + 1][1], ba);
            }
#pragma unroll
            for (int mi = 0; mi < 2; mi++)
#pragma unroll
                for (int ni = 0; ni < 8; ni++)
                    MMA_F16(acc[mi][ni], ah[mi], bh[ni]);
        }
        __syncthreads();
    }

    // --- epilogue: add b1 to the u-half (cols < DHID), write g_uv
    const int r_lo = lane >> 2;
    const int c_lo = (lane & 3) * 2;
#pragma unroll
    for (int mi = 0; mi < 2; mi++) {
        const int row_a = row0 + warp_m * 32 + mi * 16 + r_lo;
        const int row_b = row_a + 8;
#pragma unroll
        for (int ni = 0; ni < 8; ni++) {
            const int col = col0 + warp_n * 64 + ni * 8 + c_lo;
            float bx = 0.f, by = 0.f;
            if (col < DHID) { bx = __ldg(b1 + col); by = __ldg(b1 + col + 1); }
            if (row_a < NNODES)
                *(float2*)(g_uv + (size_t)row_a * NCOLS + col) =
                    make_float2(acc[mi][ni][0] + bx, acc[mi][ni][1] + by);
            if (row_b < NNODES)
                *(float2*)(g_uv + (size_t)row_b * NCOLS + col) =
                    make_float2(acc[mi][ni][2] + bx, acc[mi][ni][3] + by);
        }
    }
}

// ---------------- per-edge: out[e] = relu(u'[src] + v[dst]) . W2 + b2  (b1 folded into u')
__global__ __launch_bounds__(256)
void edge_kernel(const void* __restrict__ srcp, const void* __restrict__ dstp,
                 const float* __restrict__ W2, const float* __restrict__ b2,
                 float* __restrict__ out, int E) {
    __shared__ int s_is64;
    if (threadIdx.x == 0) {
        const int* ps = (const int*)srcp;
        const int* pd = (const int*)dstp;
        int orv = 0;
#pragma unroll
        for (int i = 1; i < 16; i += 2) orv |= ps[i] | pd[i];
        s_is64 = (orv == 0) ? 1 : 0;
    }
    __syncthreads();

    const int wid  = threadIdx.x >> 5;
    const int lane = threadIdx.x & 31;
    const int e = blockIdx.x * 8 + wid;
    if (e >= E) return;

    long long s, d;
    if (s_is64) {
        s = ((const long long*)srcp)[e];
        d = ((const long long*)dstp)[e];
    } else {
        s = (long long)((const int*)srcp)[e];
        d = (long long)((const int*)dstp)[e];
    }

    const float4* __restrict__ U = (const float4*)(g_uv + (size_t)s * NCOLS);
    const float4* __restrict__ V = (const float4*)(g_uv + (size_t)d * NCOLS + DHID);
    const float4* __restrict__ W = (const float4*)W2;

    float acc = 0.f;
#pragma unroll
    for (int i = 0; i < 8; i++) {
        const int c = i * 32 + lane;
        float4 u = U[c];
        float4 v = V[c];
        float4 w = W[c];
        acc += fmaxf(u.x + v.x, 0.f) * w.x
             + fmaxf(u.y + v.y, 0.f) * w.y
             + fmaxf(u.z + v.z, 0.f) * w.z
             + fmaxf(u.w + v.w, 0.f) * w.w;
    }
#pragma unroll
    for (int o = 16; o > 0; o >>= 1) acc += __shfl_xor_sync(0xffffffffu, acc, o);
    if (lane == 0) out[e] = acc + b2[0];
}

extern "C" void kernel_launch(void* const* d_in, const int* in_sizes, int n_in,
                              void* d_out, int out_size) {
    const float* x   = (const float*)d_in[0];
    const void*  src = d_in[1];
    const void*  dst = d_in[2];
    const float* W1  = (const float*)d_in[3];
    const float* b1  = (const float*)d_in[4];
    const float* W2  = (const float*)d_in[5];
    const float* b2  = (const float*)d_in[6];
    float* out = (float*)d_out;
    const int E = in_sizes[1];

    cudaFuncSetAttribute(gemm_mma_kernel, cudaFuncAttributeMaxDynamicSharedMemorySize, SMEM_DYN);

    const size_t n4 = (size_t)NNODES * DFEAT / 4;
    convert_x_kernel<<<(unsigned)((n4 + 255) / 256), 256>>>(x);
    convert_w_kernel<<<dim3(DFEAT / 32, NCOLS / 32), dim3(32, 8)>>>(W1);
    gemm_mma_kernel<<<dim3(NCOLS / BN, (NNODES + BM - 1) / BM), 256, SMEM_DYN>>>(b1);
    edge_kernel<<<(E + 7) / 8, 256>>>(src, dst, W2, b2, out, E);
}

// round 8
// speedup vs baseline: 2.4273x; 1.1767x over previous
#include <cuda_runtime.h>
#include <cuda_fp16.h>
#include <cstdint>

#define NNODES 50000
#define DFEAT  512
#define DHID   1024
#define NCOLS  2048

// ---------------- device scratch ----------------
__device__ __align__(16) __half g_uvh[(size_t)NNODES * NCOLS];   // node activations fp16 [N, 2048]
__device__ __align__(16) __half g_xh[(size_t)NNODES * DFEAT];    // X fp16
__device__ __align__(16) __half g_bh[(size_t)NCOLS * DFEAT];     // W1^T fp16 [2048][512]

__device__ __forceinline__ uint32_t smem_u32(const void* p) {
    uint32_t a;
    asm("{ .reg .u64 t; cvta.to.shared.u64 t, %1; cvt.u32.u64 %0, t; }" : "=r"(a) : "l"(p));
    return a;
}

#define LDSM_X4(r0, r1, r2, r3, a) \
    asm volatile("ldmatrix.sync.aligned.m8n8.x4.shared.b16 {%0,%1,%2,%3}, [%4];" \
                 : "=r"(r0), "=r"(r1), "=r"(r2), "=r"(r3) : "r"(a))

#define MMA_F16(d, a, b) \
    asm volatile("mma.sync.aligned.m16n8k16.row.col.f32.f16.f16.f32 " \
                 "{%0,%1,%2,%3}, {%4,%5,%6,%7}, {%8,%9}, {%0,%1,%2,%3};" \
                 : "+f"((d)[0]), "+f"((d)[1]), "+f"((d)[2]), "+f"((d)[3]) \
                 : "r"((a)[0]), "r"((a)[1]), "r"((a)[2]), "r"((a)[3]), "r"((b)[0]), "r"((b)[1]))

#define CP_ASYNC16(sa, ga, sz) \
    asm volatile("cp.async.cg.shared.global [%0], [%1], 16, %2;" :: "r"(sa), "l"(ga), "r"(sz))
#define CP_COMMIT() asm volatile("cp.async.commit_group;" ::: "memory")
#define CP_WAIT2()  asm volatile("cp.async.wait_group 2;" ::: "memory")
#define CP_WAIT0()  asm volatile("cp.async.wait_group 0;" ::: "memory")

__global__ __launch_bounds__(256)
void convert_x_kernel(const float* __restrict__ X) {
    size_t i = (size_t)blockIdx.x * blockDim.x + threadIdx.x;   // float4 index
    const size_t n4 = (size_t)NNODES * DFEAT / 4;
    if (i >= n4) return;
    float4 v = ((const float4*)X)[i];
    unsigned short h0 = __half_as_ushort(__float2half_rn(v.x));
    unsigned short h1 = __half_as_ushort(__float2half_rn(v.y));
    unsigned short h2 = __half_as_ushort(__float2half_rn(v.z));
    unsigned short h3 = __half_as_ushort(__float2half_rn(v.w));
    *(uint2*)(g_xh + i * 4) = make_uint2((uint32_t)h0 | ((uint32_t)h1 << 16),
                                         (uint32_t)h2 | ((uint32_t)h3 << 16));
}

// W1^T fp16:  g_bh[n][k] = W1[half(n)*512 + k][n & 1023]
__global__ __launch_bounds__(256)
void convert_w_kernel(const float* __restrict__ W1) {
    __shared__ float tile[32][33];
    const int k0 = blockIdx.x * 32;     // k in [0,512)
    const int n0 = blockIdx.y * 32;     // n in [0,2048)
    const int tx = threadIdx.x, ty = threadIdx.y;   // 32 x 8
    const int roff = (n0 >= DHID) ? DFEAT : 0;
#pragma unroll
    for (int j = 0; j < 32; j += 8) {
        int k = k0 + ty + j;
        int n = n0 + tx;
        tile[ty + j][tx] = W1[(size_t)(roff + k) * DHID + (n & (DHID - 1))];
    }
    __syncthreads();
#pragma unroll
    for (int j = 0; j < 32; j += 8) {
        int n = n0 + ty + j;
        int k = k0 + tx;
        g_bh[(size_t)n * DFEAT + k] = __float2half_rn(tile[tx][ty + j]);
    }
}

// ---------------- HMMA single-pass fp16 GEMM: g_uvh = fp16(X @ [W1_top|W1_bot] (+b1 on u-half))
#define BM 128
#define BN 128
#define BK 32
#define PITCH 80                        // 5 x 16B: conflict-free ldmatrix, no swizzle
#define TILE_B (128 * PITCH)            // 10240 B
#define OFF_AH 0
#define OFF_BH TILE_B
#define STAGE_B (2 * TILE_B)            // 20480 B
#define NSTAGE 4
#define SMEM_DYN (NSTAGE * STAGE_B)     // 81920 B

__global__ __launch_bounds__(256, 2)
void gemm_mma_kernel(const float* __restrict__ b1) {
    extern __shared__ char smem[];
    const uint32_t sbase = smem_u32(smem);
    const int tid = threadIdx.x;
    const int wid = tid >> 5, lane = tid & 31;
    const int col0 = blockIdx.x * BN;
    const int row0 = blockIdx.y * BM;
    const int warp_m = wid & 3;         // 4 m-warps of 32 rows
    const int warp_n = wid >> 2;        // 2 n-warps of 64 cols

    float acc[2][8][4];
#pragma unroll
    for (int mi = 0; mi < 2; mi++)
#pragma unroll
        for (int ni = 0; ni < 8; ni++)
#pragma unroll
            for (int q = 0; q < 4; q++) acc[mi][ni][q] = 0.f;

    const int lr  = tid >> 2;           // 0..63
    const int lc4 = tid & 3;
    auto issue_stage = [&](int kt, int slot) {
        const int k0 = kt * BK;
        const uint32_t sb = sbase + slot * STAGE_B;
#pragma unroll
        for (int h = 0; h < 2; h++) {
            const int r = lr + h * 64;
            const uint32_t so = (uint32_t)(r * PITCH + lc4 * 16);
            const size_t aoff = (size_t)(row0 + r) * DFEAT + k0 + lc4 * 8;
            const int sz = (row0 + r < NNODES) ? 16 : 0;
            CP_ASYNC16(sb + OFF_AH + so, g_xh + aoff, sz);
            const size_t boff = (size_t)(col0 + r) * DFEAT + k0 + lc4 * 8;
            CP_ASYNC16(sb + OFF_BH + so, g_bh + boff, 16);
        }
        CP_COMMIT();
    };

    const uint32_t a_off = (uint32_t)((warp_m * 32 + (lane & 15)) * PITCH + (lane >> 4) * 16);
    const int grp = lane >> 3, r8 = lane & 7;
    const uint32_t b_off = (uint32_t)((warp_n * 64 + ((grp & 2) ? 8 : 0) + r8) * PITCH
                                      + ((grp & 1) ? 16 : 0));

    issue_stage(0, 0);
    issue_stage(1, 1);
    issue_stage(2, 2);

    const int KT = DFEAT / BK;          // 16
    for (int kt = 0; kt < KT; kt++) {
        if (kt + 3 < KT) CP_WAIT2(); else CP_WAIT0();
        __syncthreads();
        if (kt + 3 < KT) issue_stage(kt + 3, (kt + 3) % NSTAGE);

        const uint32_t sb = sbase + (kt % NSTAGE) * STAGE_B;
#pragma unroll
        for (int ks = 0; ks < 2; ks++) {
            const uint32_t kb = ks * 32;
            uint32_t ah[2][4], bh[8][2];
#pragma unroll
            for (int mi = 0; mi < 2; mi++) {
                uint32_t aa = sb + a_off + mi * (16 * PITCH) + kb;
                LDSM_X4(ah[mi][0], ah[mi][1], ah[mi][2], ah[mi][3], aa + OFF_AH);
            }
#pragma unroll
            for (int p = 0; p < 4; p++) {
                uint32_t ba = sb + OFF_BH + b_off + p * (16 * PITCH) + kb;
                LDSM_X4(bh[2 * p][0], bh[2 * p][1], bh[2 * p + 1][0], bh[2 * p + 1][1], ba);
            }
#pragma unroll
            for (int mi = 0; mi < 2; mi++)
#pragma unroll
                for (int ni = 0; ni < 8; ni++)
                    MMA_F16(acc[mi][ni], ah[mi], bh[ni]);
        }
        __syncthreads();
    }

    // --- epilogue: add b1 to u-half, convert to fp16, write g_uvh
    const int r_lo = lane >> 2;
    const int c_lo = (lane & 3) * 2;
#pragma unroll
    for (int mi = 0; mi < 2; mi++) {
        const int row_a = row0 + warp_m * 32 + mi * 16 + r_lo;
        const int row_b = row_a + 8;
#pragma unroll
        for (int ni = 0; ni < 8; ni++) {
            const int col = col0 + warp_n * 64 + ni * 8 + c_lo;
            float bx = 0.f, by = 0.f;
            if (col < DHID) { bx = __ldg(b1 + col); by = __ldg(b1 + col + 1); }
            if (row_a < NNODES)
                *(__half2*)(g_uvh + (size_t)row_a * NCOLS + col) =
                    __floats2half2_rn(acc[mi][ni][0] + bx, acc[mi][ni][1] + by);
            if (row_b < NNODES)
                *(__half2*)(g_uvh + (size_t)row_b * NCOLS + col) =
                    __floats2half2_rn(acc[mi][ni][2] + bx, acc[mi][ni][3] + by);
        }
    }
}

// ---------------- per-edge: out[e] = relu(u'[src] + v[dst]) . W2 + b2  (b1 folded into u')
__global__ __launch_bounds__(256)
void edge_kernel(const void* __restrict__ srcp, const void* __restrict__ dstp,
                 const float* __restrict__ W2, const float* __restrict__ b2,
                 float* __restrict__ out, int E) {
    __shared__ int s_is64;
    if (threadIdx.x == 0) {
        const int* ps = (const int*)srcp;
        const int* pd = (const int*)dstp;
        int orv = 0;
#pragma unroll
        for (int i = 1; i < 16; i += 2) orv |= ps[i] | pd[i];
        s_is64 = (orv == 0) ? 1 : 0;
    }
    __syncthreads();

    const int wid  = threadIdx.x >> 5;
    const int lane = threadIdx.x & 31;
    const int e = blockIdx.x * 8 + wid;
    if (e >= E) return;

    long long s, d;
    if (s_is64) {
        s = ((const long long*)srcp)[e];
        d = ((const long long*)dstp)[e];
    } else {
        s = (long long)((const int*)srcp)[e];
        d = (long long)((const int*)dstp)[e];
    }

    const uint4* __restrict__ U = (const uint4*)(g_uvh + (size_t)s * NCOLS);
    const uint4* __restrict__ V = (const uint4*)(g_uvh + (size_t)d * NCOLS + DHID);
    const float4* __restrict__ W = (const float4*)W2;

    float acc = 0.f;
#pragma unroll
    for (int i = 0; i < 4; i++) {
        const int c = i * 32 + lane;        // uint4 index: 8 halves
        uint4 u = U[c];
        uint4 v = V[c];
        float4 w0 = W[c * 2];
        float4 w1 = W[c * 2 + 1];
        const __half2* uh = (const __half2*)&u;
        const __half2* vh = (const __half2*)&v;
        float2 u0 = __half22float2(uh[0]), v0 = __half22float2(vh[0]);
        float2 u1 = __half22float2(uh[1]), v1 = __half22float2(vh[1]);
        float2 u2 = __half22float2(uh[2]), v2 = __half22float2(vh[2]);
        float2 u3 = __half22float2(uh[3]), v3 = __half22float2(vh[3]);
        acc += fmaxf(u0.x + v0.x, 0.f) * w0.x
             + fmaxf(u0.y + v0.y, 0.f) * w0.y
             + fmaxf(u1.x + v1.x, 0.f) * w0.z
             + fmaxf(u1.y + v1.y, 0.f) * w0.w
             + fmaxf(u2.x + v2.x, 0.f) * w1.x
             + fmaxf(u2.y + v2.y, 0.f) * w1.y
             + fmaxf(u3.x + v3.x, 0.f) * w1.z
             + fmaxf(u3.y + v3.y, 0.f) * w1.w;
    }
#pragma unroll
    for (int o = 16; o > 0; o >>= 1) acc += __shfl_xor_sync(0xffffffffu, acc, o);
    if (lane == 0) out[e] = acc + b2[0];
}

extern "C" void kernel_launch(void* const* d_in, const int* in_sizes, int n_in,
                              void* d_out, int out_size) {
    const float* x   = (const float*)d_in[0];
    const void*  src = d_in[1];
    const void*  dst = d_in[2];
    const float* W1  = (const float*)d_in[3];
    const float* b1  = (const float*)d_in[4];
    const float* W2  = (const float*)d_in[5];
    const float* b2  = (const float*)d_in[6];
    float* out = (float*)d_out;
    const int E = in_sizes[1];

    cudaFuncSetAttribute(gemm_mma_kernel, cudaFuncAttributeMaxDynamicSharedMemorySize, SMEM_DYN);

    const size_t n4 = (size_t)NNODES * DFEAT / 4;
    convert_x_kernel<<<(unsigned)((n4 + 255) / 256), 256>>>(x);
    convert_w_kernel<<<dim3(DFEAT / 32, NCOLS / 32), dim3(32, 8)>>>(W1);
    gemm_mma_kernel<<<dim3(NCOLS / BN, (NNODES + BM - 1) / BM), 256, SMEM_DYN>>>(b1);
    edge_kernel<<<(E + 7) / 8, 256>>>(src, dst, W2, b2, out, E);
}